// round 1
// baseline (speedup 1.0000x reference)
#include <cuda_runtime.h>
#include <math.h>

#define E_DIM 1024
#define H_HEADS 16
#define D_HEAD 64
#define B_BATCH 4
#define TBQ 1024
#define TWQ 512
#define NH 64            // B_BATCH * H_HEADS
#define NR 33            // 2L+1
#define SCALE_Q 0.125f   // D^-0.5

// ---------------- scratch (device globals; no dynamic allocation) ----------
__device__ float g_qb[(size_t)NH * TBQ * D_HEAD];   // [n, t, d]
__device__ float g_kb[(size_t)NH * TBQ * D_HEAD];   // [n, t, d]
__device__ float g_vT[(size_t)NH * D_HEAD * TBQ];   // [n, d, t]
__device__ float g_qw[(size_t)NH * TWQ * D_HEAD];   // [n, w, d]
__device__ float g_kw[(size_t)NH * TWQ * D_HEAD];   // [n, w, d]
__device__ float g_arb[(size_t)NH * TBQ * NR];      // q_bpe . table
__device__ float g_arw[(size_t)NH * TWQ * NR];      // q_word . table
__device__ float g_awt[(size_t)NH * TWQ * TWQ];     // attn_word TRANSPOSED: [n, s, w]
__device__ float g_G[(size_t)NH * TBQ * TWQ];       // mapping @ attn_word: [n, q, s]
__device__ float g_attn[(size_t)NH * TBQ * TBQ];    // logits / probs (256MB)
__device__ float g_ctx[(size_t)NH * TBQ * D_HEAD];  // probs @ v

// ---------------- generic NT GEMM core --------------------------------------
// C[m][n] = sum_k la(m,k)*lb(n,k); store via sc(m,n,acc).
// Both operands K-contiguous (NT layout).
template <int BM, int BN, int BK, int TM, int TN, class LA, class LB, class SC>
__device__ __forceinline__ void gemm_core(int M, int N, int K, LA la, LB lb, SC sc) {
    constexpr int TX = BN / TN;
    constexpr int TY = BM / TM;
    constexpr int NTHR = TX * TY;
    __shared__ float As[BK][BM + 4];
    __shared__ float Bs[BK][BN + 4];

    const int tx = threadIdx.x;
    const int ty = threadIdx.y;
    const int tid = ty * TX + tx;
    const int bm = blockIdx.y * BM;
    const int bn = blockIdx.x * BN;

    float acc[TM][TN];
#pragma unroll
    for (int i = 0; i < TM; i++)
#pragma unroll
        for (int j = 0; j < TN; j++) acc[i][j] = 0.f;

    for (int k0 = 0; k0 < K; k0 += BK) {
        for (int i = tid; i < BM * BK; i += NTHR) {
            int m = i / BK, k = i % BK;
            int gm = bm + m, gk = k0 + k;
            As[k][m] = (gm < M && gk < K) ? la(gm, gk) : 0.f;
        }
        for (int i = tid; i < BN * BK; i += NTHR) {
            int n = i / BK, k = i % BK;
            int gn = bn + n, gk = k0 + k;
            Bs[k][n] = (gn < N && gk < K) ? lb(gn, gk) : 0.f;
        }
        __syncthreads();
#pragma unroll
        for (int kk = 0; kk < BK; kk++) {
            float a[TM], b[TN];
#pragma unroll
            for (int i = 0; i < TM; i += 4) {
                float4 t = *(const float4*)&As[kk][ty * TM + i];
                a[i] = t.x; a[i + 1] = t.y; a[i + 2] = t.z; a[i + 3] = t.w;
            }
#pragma unroll
            for (int j = 0; j < TN; j += 4) {
                float4 t = *(const float4*)&Bs[kk][tx * TN + j];
                b[j] = t.x; b[j + 1] = t.y; b[j + 2] = t.z; b[j + 3] = t.w;
            }
#pragma unroll
            for (int i = 0; i < TM; i++)
#pragma unroll
                for (int j = 0; j < TN; j++) acc[i][j] = fmaf(a[i], b[j], acc[i][j]);
        }
        __syncthreads();
    }

#pragma unroll
    for (int i = 0; i < TM; i++) {
        int gm = bm + ty * TM + i;
        if (gm >= M) continue;
#pragma unroll
        for (int j = 0; j < TN; j++) {
            int gn = bn + tx * TN + j;
            if (gn < N) sc(gm, gn, acc[i][j]);
        }
    }
}

__device__ __forceinline__ int clip_rel(int d) {
    return (d < -16 ? -16 : (d > 16 ? 16 : d)) + 16;
}

// ---------------- kernels ----------------------------------------------------

// X:[Trows*B, E] rows m=t*B+b. Projects with W[E,E] (row-major, uses W[n,:]),
// adds bias, scales, stores into head layout per mode.
__global__ void k_proj(const float* __restrict__ X, const float* __restrict__ W,
                       const float* __restrict__ bias, int Trows, float scale, int mode) {
    auto la = [&](int m, int k) { return X[(size_t)m * E_DIM + k]; };
    auto lb = [&](int n, int k) { return W[(size_t)n * E_DIM + k]; };
    auto sc = [&](int m, int n, float v) {
        int t = m >> 2, b = m & 3;
        int h = n >> 6, d = n & 63;
        int nn = b * H_HEADS + h;
        float r = (v + bias[n]) * scale;
        if (mode == 0)      g_qb[((size_t)nn * TBQ + t) * D_HEAD + d] = r;
        else if (mode == 1) g_kb[((size_t)nn * TBQ + t) * D_HEAD + d] = r;
        else if (mode == 2) g_vT[((size_t)nn * D_HEAD + d) * TBQ + t] = r;
        else if (mode == 3) g_qw[((size_t)nn * TWQ + t) * D_HEAD + d] = r;
        else                g_kw[((size_t)nn * TWQ + t) * D_HEAD + d] = r;
    };
    gemm_core<128, 128, 8, 8, 8>(Trows * B_BATCH, E_DIM, E_DIM, la, lb, sc);
}

// all_r[n,t,r] = q[n,t,:] . table[r,:]
__global__ void k_allr(const float* __restrict__ table, int mode) {
    int Mrows = (mode == 0) ? NH * TBQ : NH * TWQ;
    const float* Q = (mode == 0) ? g_qb : g_qw;
    float* out = (mode == 0) ? g_arb : g_arw;
    auto la = [&](int m, int k) { return Q[(size_t)m * D_HEAD + k]; };
    auto lb = [&](int n, int k) { return table[n * D_HEAD + k]; };
    auto sc = [&](int m, int n, float v) { out[(size_t)m * NR + n] = v; };
    gemm_core<128, 128, 8, 8, 8>(Mrows, NR, D_HEAD, la, lb, sc);
}

// AWT[n,s,w] = q_word[n,w,:].k_word[n,s,:] + arw[n,w,clip(s-w)]   (transposed store)
__global__ void k_attn_word() {
    int n = blockIdx.z;
    const float* qw = &g_qw[(size_t)n * TWQ * D_HEAD];
    const float* kw = &g_kw[(size_t)n * TWQ * D_HEAD];
    const float* arw = &g_arw[(size_t)n * TWQ * NR];
    float* out = &g_awt[(size_t)n * TWQ * TWQ];
    auto la = [&](int s, int k) { return kw[s * D_HEAD + k]; };
    auto lb = [&](int w, int k) { return qw[w * D_HEAD + k]; };
    auto sc = [&](int s, int w, float v) {
        out[(size_t)s * TWQ + w] = v + arw[w * NR + clip_rel(s - w)];
    };
    gemm_core<128, 128, 8, 8, 8>(TWQ, TWQ, D_HEAD, la, lb, sc);
}

// G[n,q,s] = sum_w mapping[b,q,w] * AWT[n,s,w]
__global__ void k_G(const float* __restrict__ mapping) {
    int n = blockIdx.z;
    int b = n >> 4;
    const float* Mb = &mapping[(size_t)b * TBQ * TWQ];
    const float* awt = &g_awt[(size_t)n * TWQ * TWQ];
    float* out = &g_G[(size_t)n * TBQ * TWQ];
    auto la = [&](int q, int k) { return Mb[(size_t)q * TWQ + k]; };
    auto lb = [&](int s, int k) { return awt[(size_t)s * TWQ + k]; };
    auto sc = [&](int q, int s, float v) { out[(size_t)q * TWQ + s] = v; };
    gemm_core<128, 128, 8, 8, 8>(TBQ, TWQ, TWQ, la, lb, sc);
}

// attn[n,q,kc] = q_bpe.k_bpe (K=64) + G.mapping^T (K=512) + arb[q, clip(kc-q)]
__global__ void k_attn(const float* __restrict__ mapping) {
    int n = blockIdx.z;
    int b = n >> 4;
    const float* qb = &g_qb[(size_t)n * TBQ * D_HEAD];
    const float* kb = &g_kb[(size_t)n * TBQ * D_HEAD];
    const float* G = &g_G[(size_t)n * TBQ * TWQ];
    const float* Mb = &mapping[(size_t)b * TBQ * TWQ];
    const float* arb = &g_arb[(size_t)n * TBQ * NR];
    float* out = &g_attn[(size_t)n * TBQ * TBQ];
    auto la = [&](int q, int k) {
        return (k < D_HEAD) ? qb[q * D_HEAD + k] : G[(size_t)q * TWQ + (k - D_HEAD)];
    };
    auto lb = [&](int kc, int k) {
        return (k < D_HEAD) ? kb[kc * D_HEAD + k] : Mb[(size_t)kc * TWQ + (k - D_HEAD)];
    };
    auto sc = [&](int q, int kc, float v) {
        out[(size_t)q * TBQ + kc] = v + arb[q * NR + clip_rel(kc - q)];
    };
    gemm_core<128, 128, 8, 8, 8>(TBQ, TBQ, D_HEAD + TWQ, la, lb, sc);
}

// in-place row softmax over g_attn rows of length 1024. One block per row.
__global__ void k_softmax() {
    __shared__ float red[256];
    size_t row = blockIdx.x;
    float* p = &g_attn[row * TBQ];
    int t = threadIdx.x;
    float4 v = *(float4*)&p[t * 4];
    float m = fmaxf(fmaxf(v.x, v.y), fmaxf(v.z, v.w));
    red[t] = m;
    __syncthreads();
    for (int s = 128; s > 0; s >>= 1) {
        if (t < s) red[t] = fmaxf(red[t], red[t + s]);
        __syncthreads();
    }
    m = red[0];
    __syncthreads();
    v.x = __expf(v.x - m); v.y = __expf(v.y - m);
    v.z = __expf(v.z - m); v.w = __expf(v.w - m);
    red[t] = v.x + v.y + v.z + v.w;
    __syncthreads();
    for (int s = 128; s > 0; s >>= 1) {
        if (t < s) red[t] += red[t + s];
        __syncthreads();
    }
    float inv = 1.f / red[0];
    v.x *= inv; v.y *= inv; v.z *= inv; v.w *= inv;
    *(float4*)&p[t * 4] = v;
}

// ctx[n,q,d] = sum_k probs[n,q,k] * vT[n,d,k]
__global__ void k_ctx() {
    int n = blockIdx.z;
    const float* P = &g_attn[(size_t)n * TBQ * TBQ];
    const float* vT = &g_vT[(size_t)n * D_HEAD * TBQ];
    float* out = &g_ctx[(size_t)n * TBQ * D_HEAD];
    auto la = [&](int q, int k) { return P[(size_t)q * TBQ + k]; };
    auto lb = [&](int d, int k) { return vT[(size_t)d * TBQ + k]; };
    auto sc = [&](int q, int d, float v) { out[(size_t)q * D_HEAD + d] = v; };
    gemm_core<128, 64, 16, 8, 4>(TBQ, D_HEAD, TBQ, la, lb, sc);
}

// out[t,b,e] = sum_{e'} ctx_heads[t,b,e'] * Wo[e,e'] + bo[e]
__global__ void k_out(const float* __restrict__ Wo, const float* __restrict__ bo,
                      float* __restrict__ out) {
    auto la = [&](int m, int k) {
        int t = m >> 2, b = m & 3;
        int nn = b * H_HEADS + (k >> 6);
        int d = k & 63;
        return g_ctx[((size_t)nn * TBQ + t) * D_HEAD + d];
    };
    auto lb = [&](int e, int k) { return Wo[(size_t)e * E_DIM + k]; };
    auto sc = [&](int m, int e, float v) { out[(size_t)m * E_DIM + e] = v + bo[e]; };
    gemm_core<128, 128, 8, 8, 8>(TBQ * B_BATCH, E_DIM, E_DIM, la, lb, sc);
}

// ---------------- launch ------------------------------------------------------
extern "C" void kernel_launch(void* const* d_in, const int* in_sizes, int n_in,
                              void* d_out, int out_size) {
    const float* query_bpe  = (const float*)d_in[0];
    const float* query_word = (const float*)d_in[1];
    const float* mapping    = (const float*)d_in[2];
    const float* Wq_bpe  = (const float*)d_in[3];
    const float* bq_bpe  = (const float*)d_in[4];
    const float* Wk_bpe  = (const float*)d_in[5];
    const float* bk_bpe  = (const float*)d_in[6];
    const float* Wq_word = (const float*)d_in[7];
    const float* bq_word = (const float*)d_in[8];
    const float* Wk_word = (const float*)d_in[9];
    const float* bk_word = (const float*)d_in[10];
    const float* Wv = (const float*)d_in[11];
    const float* bv = (const float*)d_in[12];
    const float* Wo = (const float*)d_in[13];
    const float* bo = (const float*)d_in[14];
    const float* rel_keys = (const float*)d_in[15];
    float* out = (float*)d_out;

    dim3 blk(16, 16);

    // projections -> head layout
    k_proj<<<dim3(8, 32), blk>>>(query_bpe,  Wq_bpe,  bq_bpe,  TBQ, SCALE_Q, 0);
    k_proj<<<dim3(8, 32), blk>>>(query_bpe,  Wk_bpe,  bk_bpe,  TBQ, 1.f,     1);
    k_proj<<<dim3(8, 32), blk>>>(query_bpe,  Wv,      bv,      TBQ, 1.f,     2);
    k_proj<<<dim3(8, 16), blk>>>(query_word, Wq_word, bq_word, TWQ, SCALE_Q, 3);
    k_proj<<<dim3(8, 16), blk>>>(query_word, Wk_word, bk_word, TWQ, 1.f,     4);

    // relative-position tables
    k_allr<<<dim3(1, 512), blk>>>(rel_keys, 0);
    k_allr<<<dim3(1, 256), blk>>>(rel_keys, 1);

    // word attention logits (stored transposed), then fused alignment chain
    k_attn_word<<<dim3(4, 4, NH), blk>>>();
    k_G<<<dim3(4, 8, NH), blk>>>(mapping);
    k_attn<<<dim3(8, 8, NH), blk>>>(mapping);

    // softmax over keys
    k_softmax<<<NH * TBQ, 256>>>();

    // probs @ V, output projection
    k_ctx<<<dim3(1, 8, NH), blk>>>();
    k_out<<<dim3(8, 32), blk>>>(Wo, bo, out);
}

// round 2
// speedup vs baseline: 1.9844x; 1.9844x over previous
#include <cuda_runtime.h>
#include <math.h>

#define E_DIM 1024
#define H_HEADS 16
#define D_HEAD 64
#define B_BATCH 4
#define TBQ 1024
#define TWQ 512
#define NH 64            // B_BATCH * H_HEADS
#define NR 33            // 2L+1
#define SCALE_Q 0.125f   // D^-0.5

// ---------------- scratch (device globals; no dynamic allocation) ----------
__device__ float g_qb[(size_t)NH * TBQ * D_HEAD];   // [n, t, d]
__device__ float g_kb[(size_t)NH * TBQ * D_HEAD];   // [n, t, d]
__device__ float g_vT[(size_t)NH * D_HEAD * TBQ];   // [n, d, t]
__device__ float g_qw[(size_t)NH * TWQ * D_HEAD];   // [n, w, d]
__device__ float g_kw[(size_t)NH * TWQ * D_HEAD];   // [n, w, d]
__device__ float g_arb[(size_t)NH * TBQ * NR];      // q_bpe . table
__device__ float g_arw[(size_t)NH * TWQ * NR];      // q_word . table
__device__ float g_awt[(size_t)NH * TWQ * TWQ];     // attn_word TRANSPOSED: [n, s, w]
__device__ float g_G[(size_t)NH * TBQ * TWQ];       // mapping @ attn_word: [n, q, s]
__device__ float g_attn[(size_t)NH * TBQ * TBQ];    // logits / probs (256MB)
__device__ float g_ctx[(size_t)NH * TBQ * D_HEAD];  // probs @ v

// ---------------- packed f32x2 helpers (Blackwell FFMA2) --------------------
__device__ __forceinline__ unsigned long long pk2(float x, float y) {
    unsigned long long r;
    asm("mov.b64 %0, {%1, %2};" : "=l"(r) : "f"(x), "f"(y));
    return r;
}
__device__ __forceinline__ void upk2(unsigned long long v, float& x, float& y) {
    asm("mov.b64 {%0, %1}, %2;" : "=f"(x), "=f"(y) : "l"(v));
}
__device__ __forceinline__ void fma2(unsigned long long& c, unsigned long long a,
                                     unsigned long long b) {
    asm("fma.rn.f32x2 %0, %1, %2, %0;" : "+l"(c) : "l"(a), "l"(b));
}

// ---------------- generic NT GEMM core (FFMA2, double-buffered) -------------
// C[m][n] = sum_k la(m,k)*lb(n,k); store via sc(m,n,acc).
// Both operands K-contiguous (NT). Accumulators packed as row-pairs in b64.
template <int BM, int BN, int BK, int TM, int TN, class LA, class LB, class SC>
__device__ __forceinline__ void gemm_core(int M, int N, int K, LA la, LB lb, SC sc) {
    constexpr int TX = BN / TN;
    constexpr int TY = BM / TM;
    constexpr int NTHR = TX * TY;
    constexpr int LAN = BM * BK / NTHR;
    constexpr int LBN = BN * BK / NTHR;
    static_assert(TM % 4 == 0 && TN % 4 == 0, "tile shape");

    __shared__ float As[2][BK][BM + 4];
    __shared__ float Bs[2][BK][BN + 4];

    const int tid = threadIdx.x;
    const int tx = tid % TX;
    const int ty = tid / TX;
    const int bm = blockIdx.y * BM;
    const int bn = blockIdx.x * BN;

    unsigned long long acc[TM / 2][TN];
#pragma unroll
    for (int i = 0; i < TM / 2; i++)
#pragma unroll
        for (int j = 0; j < TN; j++) acc[i][j] = 0ull;

    float ra[LAN], rb[LBN];
    const int KT = (K + BK - 1) / BK;

    auto fetch = [&](int kt) {
#pragma unroll
        for (int l = 0; l < LAN; l++) {
            int i = tid + l * NTHR;
            int m = i / BK, k = i % BK;
            int gm = bm + m, gk = kt * BK + k;
            ra[l] = (gm < M && gk < K) ? la(gm, gk) : 0.f;
        }
#pragma unroll
        for (int l = 0; l < LBN; l++) {
            int i = tid + l * NTHR;
            int n = i / BK, k = i % BK;
            int gn = bn + n, gk = kt * BK + k;
            rb[l] = (gn < N && gk < K) ? lb(gn, gk) : 0.f;
        }
    };
    auto stage = [&](int buf) {
#pragma unroll
        for (int l = 0; l < LAN; l++) {
            int i = tid + l * NTHR;
            As[buf][i % BK][i / BK] = ra[l];
        }
#pragma unroll
        for (int l = 0; l < LBN; l++) {
            int i = tid + l * NTHR;
            Bs[buf][i % BK][i / BK] = rb[l];
        }
    };

    fetch(0);
    stage(0);
    __syncthreads();

    for (int kt = 0; kt < KT; kt++) {
        const int cur = kt & 1;
        if (kt + 1 < KT) fetch(kt + 1);
#pragma unroll
        for (int kk = 0; kk < BK; kk++) {
            // A row-pairs: packed b64 straight out of shared (LDS.128)
            unsigned long long a2[TM / 2];
            const ulonglong2* ap =
                reinterpret_cast<const ulonglong2*>(&As[cur][kk][ty * TM]);
#pragma unroll
            for (int i = 0; i < TM / 4; i++) {
                ulonglong2 t = ap[i];
                a2[2 * i] = t.x;
                a2[2 * i + 1] = t.y;
            }
            float b[TN];
            const float4* bp =
                reinterpret_cast<const float4*>(&Bs[cur][kk][tx * TN]);
#pragma unroll
            for (int j = 0; j < TN / 4; j++) {
                float4 t = bp[j];
                b[4 * j] = t.x; b[4 * j + 1] = t.y;
                b[4 * j + 2] = t.z; b[4 * j + 3] = t.w;
            }
#pragma unroll
            for (int j = 0; j < TN; j++) {
                unsigned long long bd = pk2(b[j], b[j]);
#pragma unroll
                for (int i = 0; i < TM / 2; i++) fma2(acc[i][j], a2[i], bd);
            }
        }
        if (kt + 1 < KT) stage((kt + 1) & 1);
        __syncthreads();
    }

#pragma unroll
    for (int i = 0; i < TM / 2; i++) {
        int gm0 = bm + ty * TM + 2 * i;
#pragma unroll
        for (int j = 0; j < TN; j++) {
            int gn = bn + tx * TN + j;
            if (gn >= N) continue;
            float lo, hi;
            upk2(acc[i][j], lo, hi);
            if (gm0 < M) sc(gm0, gn, lo);
            if (gm0 + 1 < M) sc(gm0 + 1, gn, hi);
        }
    }
}

__device__ __forceinline__ int clip_rel(int d) {
    return (d < -16 ? -16 : (d > 16 ? 16 : d)) + 16;
}

// ---------------- kernels ----------------------------------------------------

// X:[Trows*B, E] rows m=t*B+b. Projects with W[E,E] row-major (uses W[n,:]),
// adds bias, scales, stores into head layout per mode.
__global__ void __launch_bounds__(128)
k_proj(const float* __restrict__ X, const float* __restrict__ W,
       const float* __restrict__ bias, int Trows, float scale, int mode) {
    auto la = [&](int m, int k) { return X[(size_t)m * E_DIM + k]; };
    auto lb = [&](int n, int k) { return W[(size_t)n * E_DIM + k]; };
    auto sc = [&](int m, int n, float v) {
        int t = m >> 2, b = m & 3;
        int h = n >> 6, d = n & 63;
        int nn = b * H_HEADS + h;
        float r = (v + bias[n]) * scale;
        if (mode == 0)      g_qb[((size_t)nn * TBQ + t) * D_HEAD + d] = r;
        else if (mode == 1) g_kb[((size_t)nn * TBQ + t) * D_HEAD + d] = r;
        else if (mode == 2) g_vT[((size_t)nn * D_HEAD + d) * TBQ + t] = r;
        else if (mode == 3) g_qw[((size_t)nn * TWQ + t) * D_HEAD + d] = r;
        else                g_kw[((size_t)nn * TWQ + t) * D_HEAD + d] = r;
    };
    gemm_core<128, 128, 16, 16, 8>(Trows * B_BATCH, E_DIM, E_DIM, la, lb, sc);
}

// all_r[n,t,r] = q[n,t,:] . table[r,:]
__global__ void __launch_bounds__(128)
k_allr(const float* __restrict__ table, int mode) {
    int Mrows = (mode == 0) ? NH * TBQ : NH * TWQ;
    const float* Q = (mode == 0) ? g_qb : g_qw;
    float* out = (mode == 0) ? g_arb : g_arw;
    auto la = [&](int m, int k) { return Q[(size_t)m * D_HEAD + k]; };
    auto lb = [&](int n, int k) { return table[n * D_HEAD + k]; };
    auto sc = [&](int m, int n, float v) { out[(size_t)m * NR + n] = v; };
    gemm_core<128, 128, 16, 16, 8>(Mrows, NR, D_HEAD, la, lb, sc);
}

// AWT[n,s,w] = q_word[n,w,:].k_word[n,s,:] + arw[n,w,clip(s-w)] (transposed store)
__global__ void __launch_bounds__(128) k_attn_word() {
    int n = blockIdx.z;
    const float* qw = &g_qw[(size_t)n * TWQ * D_HEAD];
    const float* kw = &g_kw[(size_t)n * TWQ * D_HEAD];
    const float* arw = &g_arw[(size_t)n * TWQ * NR];
    float* out = &g_awt[(size_t)n * TWQ * TWQ];
    auto la = [&](int s, int k) { return kw[s * D_HEAD + k]; };
    auto lb = [&](int w, int k) { return qw[w * D_HEAD + k]; };
    auto sc = [&](int s, int w, float v) {
        out[(size_t)s * TWQ + w] = v + arw[w * NR + clip_rel(s - w)];
    };
    gemm_core<128, 128, 16, 16, 8>(TWQ, TWQ, D_HEAD, la, lb, sc);
}

// G[n,q,s] = sum_w mapping[b,q,w] * AWT[n,s,w]
__global__ void __launch_bounds__(128) k_G(const float* __restrict__ mapping) {
    int n = blockIdx.z;
    int b = n >> 4;
    const float* Mb = &mapping[(size_t)b * TBQ * TWQ];
    const float* awt = &g_awt[(size_t)n * TWQ * TWQ];
    float* out = &g_G[(size_t)n * TBQ * TWQ];
    auto la = [&](int q, int k) { return Mb[(size_t)q * TWQ + k]; };
    auto lb = [&](int s, int k) { return awt[(size_t)s * TWQ + k]; };
    auto sc = [&](int q, int s, float v) { out[(size_t)q * TWQ + s] = v; };
    gemm_core<128, 128, 16, 16, 8>(TBQ, TWQ, TWQ, la, lb, sc);
}

// attn[n,q,kc] = q_bpe.k_bpe (K=64) + G.mapping^T (K=512) + arb[q, clip(kc-q)]
__global__ void __launch_bounds__(128) k_attn(const float* __restrict__ mapping) {
    int n = blockIdx.z;
    int b = n >> 4;
    const float* qb = &g_qb[(size_t)n * TBQ * D_HEAD];
    const float* kb = &g_kb[(size_t)n * TBQ * D_HEAD];
    const float* G = &g_G[(size_t)n * TBQ * TWQ];
    const float* Mb = &mapping[(size_t)b * TBQ * TWQ];
    const float* arb = &g_arb[(size_t)n * TBQ * NR];
    float* out = &g_attn[(size_t)n * TBQ * TBQ];
    auto la = [&](int q, int k) {
        return (k < D_HEAD) ? qb[q * D_HEAD + k] : G[(size_t)q * TWQ + (k - D_HEAD)];
    };
    auto lb = [&](int kc, int k) {
        return (k < D_HEAD) ? kb[kc * D_HEAD + k] : Mb[(size_t)kc * TWQ + (k - D_HEAD)];
    };
    auto sc = [&](int q, int kc, float v) {
        out[(size_t)q * TBQ + kc] = v + arb[q * NR + clip_rel(kc - q)];
    };
    gemm_core<128, 128, 16, 16, 8>(TBQ, TBQ, D_HEAD + TWQ, la, lb, sc);
}

// in-place row softmax over g_attn rows of length 1024. One block per row.
__global__ void k_softmax() {
    __shared__ float red[256];
    size_t row = blockIdx.x;
    float* p = &g_attn[row * TBQ];
    int t = threadIdx.x;
    float4 v = *(float4*)&p[t * 4];
    float m = fmaxf(fmaxf(v.x, v.y), fmaxf(v.z, v.w));
    red[t] = m;
    __syncthreads();
    for (int s = 128; s > 0; s >>= 1) {
        if (t < s) red[t] = fmaxf(red[t], red[t + s]);
        __syncthreads();
    }
    m = red[0];
    __syncthreads();
    v.x = __expf(v.x - m); v.y = __expf(v.y - m);
    v.z = __expf(v.z - m); v.w = __expf(v.w - m);
    red[t] = v.x + v.y + v.z + v.w;
    __syncthreads();
    for (int s = 128; s > 0; s >>= 1) {
        if (t < s) red[t] += red[t + s];
        __syncthreads();
    }
    float inv = 1.f / red[0];
    v.x *= inv; v.y *= inv; v.z *= inv; v.w *= inv;
    *(float4*)&p[t * 4] = v;
}

// ctx[n,q,d] = sum_k probs[n,q,k] * vT[n,d,k]
__global__ void __launch_bounds__(128) k_ctx() {
    int n = blockIdx.z;
    const float* P = &g_attn[(size_t)n * TBQ * TBQ];
    const float* vT = &g_vT[(size_t)n * D_HEAD * TBQ];
    float* out = &g_ctx[(size_t)n * TBQ * D_HEAD];
    auto la = [&](int q, int k) { return P[(size_t)q * TBQ + k]; };
    auto lb = [&](int d, int k) { return vT[(size_t)d * TBQ + k]; };
    auto sc = [&](int q, int d, float v) { out[(size_t)q * D_HEAD + d] = v; };
    gemm_core<128, 64, 16, 8, 8>(TBQ, D_HEAD, TBQ, la, lb, sc);
}

// out[t,b,e] = sum_{e'} ctx_heads[t,b,e'] * Wo[e,e'] + bo[e]
__global__ void __launch_bounds__(128)
k_out(const float* __restrict__ Wo, const float* __restrict__ bo,
      float* __restrict__ out) {
    auto la = [&](int m, int k) {
        int t = m >> 2, b = m & 3;
        int nn = b * H_HEADS + (k >> 6);
        int d = k & 63;
        return g_ctx[((size_t)nn * TBQ + t) * D_HEAD + d];
    };
    auto lb = [&](int e, int k) { return Wo[(size_t)e * E_DIM + k]; };
    auto sc = [&](int m, int e, float v) { out[(size_t)m * E_DIM + e] = v + bo[e]; };
    gemm_core<128, 128, 16, 16, 8>(TBQ * B_BATCH, E_DIM, E_DIM, la, lb, sc);
}

// ---------------- launch ------------------------------------------------------
extern "C" void kernel_launch(void* const* d_in, const int* in_sizes, int n_in,
                              void* d_out, int out_size) {
    const float* query_bpe  = (const float*)d_in[0];
    const float* query_word = (const float*)d_in[1];
    const float* mapping    = (const float*)d_in[2];
    const float* Wq_bpe  = (const float*)d_in[3];
    const float* bq_bpe  = (const float*)d_in[4];
    const float* Wk_bpe  = (const float*)d_in[5];
    const float* bk_bpe  = (const float*)d_in[6];
    const float* Wq_word = (const float*)d_in[7];
    const float* bq_word = (const float*)d_in[8];
    const float* Wk_word = (const float*)d_in[9];
    const float* bk_word = (const float*)d_in[10];
    const float* Wv = (const float*)d_in[11];
    const float* bv = (const float*)d_in[12];
    const float* Wo = (const float*)d_in[13];
    const float* bo = (const float*)d_in[14];
    const float* rel_keys = (const float*)d_in[15];
    float* out = (float*)d_out;

    const int THR = 128;

    // projections -> head layout
    k_proj<<<dim3(8, 32), THR>>>(query_bpe,  Wq_bpe,  bq_bpe,  TBQ, SCALE_Q, 0);
    k_proj<<<dim3(8, 32), THR>>>(query_bpe,  Wk_bpe,  bk_bpe,  TBQ, 1.f,     1);
    k_proj<<<dim3(8, 32), THR>>>(query_bpe,  Wv,      bv,      TBQ, 1.f,     2);
    k_proj<<<dim3(8, 16), THR>>>(query_word, Wq_word, bq_word, TWQ, SCALE_Q, 3);
    k_proj<<<dim3(8, 16), THR>>>(query_word, Wk_word, bk_word, TWQ, 1.f,     4);

    // relative-position tables
    k_allr<<<dim3(1, 512), THR>>>(rel_keys, 0);
    k_allr<<<dim3(1, 256), THR>>>(rel_keys, 1);

    // word attention logits (stored transposed), then fused alignment chain
    k_attn_word<<<dim3(4, 4, NH), THR>>>();
    k_G<<<dim3(4, 8, NH), THR>>>(mapping);
    k_attn<<<dim3(8, 8, NH), THR>>>(mapping);

    // softmax over keys
    k_softmax<<<NH * TBQ, 256>>>();

    // probs @ V, output projection
    k_ctx<<<dim3(1, 8, NH), THR>>>();
    k_out<<<dim3(8, 32), THR>>>(Wo, bo, out);
}

// round 5
// speedup vs baseline: 2.0820x; 1.0492x over previous
#include <cuda_runtime.h>
#include <cstdint>
#include <math.h>

#define E_DIM 1024
#define H_HEADS 16
#define D_HEAD 64
#define B_BATCH 4
#define TBQ 1024
#define TWQ 512
#define NH 64            // B_BATCH * H_HEADS
#define NR 33            // 2L+1
#define SCALE_Q 0.125f   // D^-0.5

// ---------------- scratch (device globals; no dynamic allocation) ----------
__device__ float g_qb[(size_t)NH * TBQ * D_HEAD];   // [n, t, d]
__device__ float g_kb[(size_t)NH * TBQ * D_HEAD];   // [n, t, d]
__device__ float g_vT[(size_t)NH * D_HEAD * TBQ];   // [n, d, t]
__device__ float g_qw[(size_t)NH * TWQ * D_HEAD];   // [n, w, d]
__device__ float g_kw[(size_t)NH * TWQ * D_HEAD];   // [n, w, d]
__device__ float g_arb[(size_t)NH * TBQ * NR];      // q_bpe . table
__device__ float g_arw[(size_t)NH * TWQ * NR];      // q_word . table
__device__ float g_awt[(size_t)NH * TWQ * TWQ];     // attn_word TRANSPOSED: [n, s, w]
__device__ float g_G[(size_t)NH * TBQ * TWQ];       // mapping @ attn_word: [n, q, s]
__device__ float g_attn[(size_t)NH * TBQ * TBQ];    // logits / probs (256MB)
__device__ float g_ctx[(size_t)NH * TBQ * D_HEAD];  // probs @ v

// ---------------- helpers -----------------------------------------------------
__device__ __forceinline__ float4 ld4(const float* p) {
    return *reinterpret_cast<const float4*>(p);
}
__device__ __forceinline__ float tf32f(float x) {
    uint32_t r;
    asm("cvt.rna.tf32.f32 %0, %1;" : "=r"(r) : "f"(x));
    return __uint_as_float(r);
}
__device__ __forceinline__ int clip_rel(int d) {
    return (d < -16 ? -16 : (d > 16 ? 16 : d)) + 16;
}

// mma.sync tf32 m16n8k8 (baseline PTX -> HMMA fallback on sm_103)
__device__ __forceinline__ void mma8(float* c, const uint32_t* a, const uint32_t* b) {
    asm volatile(
        "mma.sync.aligned.m16n8k8.row.col.f32.tf32.tf32.f32 "
        "{%0,%1,%2,%3}, {%4,%5,%6,%7}, {%8,%9}, {%0,%1,%2,%3};"
        : "+f"(c[0]), "+f"(c[1]), "+f"(c[2]), "+f"(c[3])
        : "r"(a[0]), "r"(a[1]), "r"(a[2]), "r"(a[3]), "r"(b[0]), "r"(b[1]));
}

// packed f32x2 (FFMA2) for the fallback core
__device__ __forceinline__ unsigned long long pk2(float x, float y) {
    unsigned long long r;
    asm("mov.b64 %0, {%1, %2};" : "=l"(r) : "f"(x), "f"(y));
    return r;
}
__device__ __forceinline__ void upk2(unsigned long long v, float& x, float& y) {
    asm("mov.b64 {%0, %1}, %2;" : "=f"(x), "=f"(y) : "l"(v));
}
__device__ __forceinline__ void fma2(unsigned long long& c, unsigned long long a,
                                     unsigned long long b) {
    asm("fma.rn.f32x2 %0, %1, %2, %0;" : "+l"(c) : "l"(a), "l"(b));
}

// ---------------- mma.sync 3xTF32 NT GEMM core -------------------------------
// C[m][n] = sum_k A[m,k]*B[n,k], ~fp32 precision via 3xTF32 split.
// All of M, N, K must be exact multiples of BM, BN, BK (no bounds checks).
// la4/lb4 return float4 at (row, k4) with k = 4*k4. sc(m,n,val) stores.
// 256 threads. Warp grid (BM/WM) x (BN/WN) == 8.
template <int BM, int BN, int BK, int WM, int WN, class LA4, class LB4, class SC>
__device__ __forceinline__ void gemm_mma(int K, LA4 la4, LB4 lb4, SC sc) {
    constexpr int NTHR = 256;
    constexpr int PAD = 4;
    constexpr int LDA = BM + PAD;
    constexpr int LDB = BN + PAD;
    constexpr int ASZ = BK * LDA;
    constexpr int BSZ = BK * LDB;
    constexpr int BUF = 2 * (ASZ + BSZ);   // floats per buffer (Ah,Al,Bh,Bl)
    constexpr int K4 = BK / 4;
    constexpr int A4 = BM * K4 / NTHR;     // float4 fetches/thread for A
    constexpr int B4 = BN * K4 / NTHR;
    constexpr int MT = WM / 16;
    constexpr int NT = WN / 8;
    constexpr int WGM = BM / WM;
    static_assert((BM / WM) * (BN / WN) == 8, "warp grid");

    extern __shared__ float smf[];

    const int tid = threadIdx.x;
    const int lane = tid & 31;
    const int wid = tid >> 5;
    const int wm0 = (wid % WGM) * WM;
    const int wn0 = (wid / WGM) * WN;
    const int bm = blockIdx.y * BM;
    const int bn = blockIdx.x * BN;
    const int g = lane >> 2;     // group id (row / col within fragment)
    const int t4 = lane & 3;     // thread-in-group (k index)

    float acc[MT][NT][4];
#pragma unroll
    for (int i = 0; i < MT; i++)
#pragma unroll
        for (int j = 0; j < NT; j++) {
            acc[i][j][0] = 0.f; acc[i][j][1] = 0.f;
            acc[i][j][2] = 0.f; acc[i][j][3] = 0.f;
        }

    float4 va[A4], vb[B4];
    const int KT = K / BK;

    auto fetch = [&](int kt) {
#pragma unroll
        for (int l = 0; l < A4; l++) {
            int f = tid + l * NTHR;
            va[l] = la4(bm + f / K4, kt * K4 + (f % K4));
        }
#pragma unroll
        for (int l = 0; l < B4; l++) {
            int f = tid + l * NTHR;
            vb[l] = lb4(bn + f / K4, kt * K4 + (f % K4));
        }
    };
    auto stage = [&](int buf) {
        float* Ah = smf + buf * BUF;
        float* Al = Ah + ASZ;
        float* Bh = Al + ASZ;
        float* Bl = Bh + BSZ;
#pragma unroll
        for (int l = 0; l < A4; l++) {
            int f = tid + l * NTHR;
            int m = f / K4, k = (f % K4) * 4;
            float v[4] = {va[l].x, va[l].y, va[l].z, va[l].w};
#pragma unroll
            for (int j = 0; j < 4; j++) {
                float h = tf32f(v[j]);
                Ah[(k + j) * LDA + m] = h;
                Al[(k + j) * LDA + m] = tf32f(v[j] - h);
            }
        }
#pragma unroll
        for (int l = 0; l < B4; l++) {
            int f = tid + l * NTHR;
            int n = f / K4, k = (f % K4) * 4;
            float v[4] = {vb[l].x, vb[l].y, vb[l].z, vb[l].w};
#pragma unroll
            for (int j = 0; j < 4; j++) {
                float h = tf32f(v[j]);
                Bh[(k + j) * LDB + n] = h;
                Bl[(k + j) * LDB + n] = tf32f(v[j] - h);
            }
        }
    };

    fetch(0);
    stage(0);
    __syncthreads();

    for (int kt = 0; kt < KT; kt++) {
        const int cur = kt & 1;
        if (kt + 1 < KT) fetch(kt + 1);
        const float* Ah = smf + cur * BUF;
        const float* Al = Ah + ASZ;
        const float* Bh = Al + ASZ;
        const float* Bl = Bh + BSZ;
#pragma unroll
        for (int ks = 0; ks < BK / 8; ks++) {
            const int k0 = ks * 8;
            uint32_t ah[MT][4], al[MT][4];
#pragma unroll
            for (int mt = 0; mt < MT; mt++) {
                int m = wm0 + mt * 16 + g;
                ah[mt][0] = __float_as_uint(Ah[(k0 + t4) * LDA + m]);
                ah[mt][1] = __float_as_uint(Ah[(k0 + t4) * LDA + m + 8]);
                ah[mt][2] = __float_as_uint(Ah[(k0 + t4 + 4) * LDA + m]);
                ah[mt][3] = __float_as_uint(Ah[(k0 + t4 + 4) * LDA + m + 8]);
                al[mt][0] = __float_as_uint(Al[(k0 + t4) * LDA + m]);
                al[mt][1] = __float_as_uint(Al[(k0 + t4) * LDA + m + 8]);
                al[mt][2] = __float_as_uint(Al[(k0 + t4 + 4) * LDA + m]);
                al[mt][3] = __float_as_uint(Al[(k0 + t4 + 4) * LDA + m + 8]);
            }
#pragma unroll
            for (int nt = 0; nt < NT; nt++) {
                int n = wn0 + nt * 8 + g;
                uint32_t bh[2], bl[2];
                bh[0] = __float_as_uint(Bh[(k0 + t4) * LDB + n]);
                bh[1] = __float_as_uint(Bh[(k0 + t4 + 4) * LDB + n]);
                bl[0] = __float_as_uint(Bl[(k0 + t4) * LDB + n]);
                bl[1] = __float_as_uint(Bl[(k0 + t4 + 4) * LDB + n]);
#pragma unroll
                for (int mt = 0; mt < MT; mt++) {
                    mma8(acc[mt][nt], ah[mt], bh);
                    mma8(acc[mt][nt], ah[mt], bl);
                    mma8(acc[mt][nt], al[mt], bh);
                }
            }
        }
        if (kt + 1 < KT) stage((kt + 1) & 1);
        __syncthreads();
    }

    // epilogue: c0,c1 -> (row, col), (row, col+1); c2,c3 -> row+8
#pragma unroll
    for (int mt = 0; mt < MT; mt++) {
#pragma unroll
        for (int nt = 0; nt < NT; nt++) {
            int row = bm + wm0 + mt * 16 + g;
            int col = bn + wn0 + nt * 8 + 2 * t4;
            sc(row, col, acc[mt][nt][0]);
            sc(row, col + 1, acc[mt][nt][1]);
            sc(row + 8, col, acc[mt][nt][2]);
            sc(row + 8, col + 1, acc[mt][nt][3]);
        }
    }
}

// ---------------- FFMA2 core (proven; used for N=33 rel-table GEMM) ---------
template <int BM, int BN, int BK, int TM, int TN, class LA, class LB, class SC>
__device__ __forceinline__ void gemm_ffma2(int M, int N, int K, LA la, LB lb, SC sc) {
    constexpr int TX = BN / TN;
    constexpr int TY = BM / TM;
    constexpr int NTHR = TX * TY;
    constexpr int LAN = BM * BK / NTHR;
    constexpr int LBN = BN * BK / NTHR;

    __shared__ float As[2][BK][BM + 4];
    __shared__ float Bs[2][BK][BN + 4];

    const int tid = threadIdx.x;
    const int tx = tid % TX;
    const int ty = tid / TX;
    const int bm = blockIdx.y * BM;
    const int bn = blockIdx.x * BN;

    unsigned long long acc[TM / 2][TN];
#pragma unroll
    for (int i = 0; i < TM / 2; i++)
#pragma unroll
        for (int j = 0; j < TN; j++) acc[i][j] = 0ull;

    float ra[LAN], rb[LBN];
    const int KT = (K + BK - 1) / BK;

    auto fetch = [&](int kt) {
#pragma unroll
        for (int l = 0; l < LAN; l++) {
            int i = tid + l * NTHR;
            int m = i / BK, k = i % BK;
            int gm = bm + m, gk = kt * BK + k;
            ra[l] = (gm < M && gk < K) ? la(gm, gk) : 0.f;
        }
#pragma unroll
        for (int l = 0; l < LBN; l++) {
            int i = tid + l * NTHR;
            int n = i / BK, k = i % BK;
            int gn = bn + n, gk = kt * BK + k;
            rb[l] = (gn < N && gk < K) ? lb(gn, gk) : 0.f;
        }
    };
    auto stage = [&](int b) {
#pragma unroll
        for (int l = 0; l < LAN; l++) {
            int i = tid + l * NTHR;
            As[b][i % BK][i / BK] = ra[l];
        }
#pragma unroll
        for (int l = 0; l < LBN; l++) {
            int i = tid + l * NTHR;
            Bs[b][i % BK][i / BK] = rb[l];
        }
    };

    fetch(0); stage(0); __syncthreads();

    for (int kt = 0; kt < KT; kt++) {
        const int cur = kt & 1;
        if (kt + 1 < KT) fetch(kt + 1);
#pragma unroll
        for (int kk = 0; kk < BK; kk++) {
            unsigned long long a2[TM / 2];
            const ulonglong2* ap =
                reinterpret_cast<const ulonglong2*>(&As[cur][kk][ty * TM]);
#pragma unroll
            for (int i = 0; i < TM / 4; i++) {
                ulonglong2 t = ap[i];
                a2[2 * i] = t.x; a2[2 * i + 1] = t.y;
            }
            float b[TN];
            const float4* bp = reinterpret_cast<const float4*>(&Bs[cur][kk][tx * TN]);
#pragma unroll
            for (int j = 0; j < TN / 4; j++) {
                float4 t = bp[j];
                b[4 * j] = t.x; b[4 * j + 1] = t.y; b[4 * j + 2] = t.z; b[4 * j + 3] = t.w;
            }
#pragma unroll
            for (int j = 0; j < TN; j++) {
                unsigned long long bd = pk2(b[j], b[j]);
#pragma unroll
                for (int i = 0; i < TM / 2; i++) fma2(acc[i][j], a2[i], bd);
            }
        }
        if (kt + 1 < KT) stage((kt + 1) & 1);
        __syncthreads();
    }

#pragma unroll
    for (int i = 0; i < TM / 2; i++) {
        int gm0 = bm + ty * TM + 2 * i;
#pragma unroll
        for (int j = 0; j < TN; j++) {
            int gn = bn + tx * TN + j;
            if (gn >= N) continue;
            float lo, hi;
            upk2(acc[i][j], lo, hi);
            if (gm0 < M) sc(gm0, gn, lo);
            if (gm0 + 1 < M) sc(gm0 + 1, gn, hi);
        }
    }
}

// ---------------- kernels ----------------------------------------------------

__global__ void __launch_bounds__(256)
k_proj(const float* __restrict__ X, const float* __restrict__ W,
       const float* __restrict__ bias, float scale, int mode) {
    auto la4 = [&](int m, int k4) { return ld4(&X[(size_t)m * E_DIM + k4 * 4]); };
    auto lb4 = [&](int n, int k4) { return ld4(&W[(size_t)n * E_DIM + k4 * 4]); };
    auto sc = [&](int m, int n, float v) {
        int t = m >> 2, b = m & 3;
        int h = n >> 6, d = n & 63;
        int nn = b * H_HEADS + h;
        float r = (v + bias[n]) * scale;
        if (mode == 0)      g_qb[((size_t)nn * TBQ + t) * D_HEAD + d] = r;
        else if (mode == 1) g_kb[((size_t)nn * TBQ + t) * D_HEAD + d] = r;
        else if (mode == 2) g_vT[((size_t)nn * D_HEAD + d) * TBQ + t] = r;
        else if (mode == 3) g_qw[((size_t)nn * TWQ + t) * D_HEAD + d] = r;
        else                g_kw[((size_t)nn * TWQ + t) * D_HEAD + d] = r;
    };
    gemm_mma<128, 128, 16, 64, 32>(E_DIM, la4, lb4, sc);
}

// rel tables: N=33 -> FFMA2 core (bounds-checked)
__global__ void __launch_bounds__(128)
k_allr(const float* __restrict__ table, int mode) {
    int Mrows = (mode == 0) ? NH * TBQ : NH * TWQ;
    const float* Q = (mode == 0) ? g_qb : g_qw;
    float* out = (mode == 0) ? g_arb : g_arw;
    auto la = [&](int m, int k) { return Q[(size_t)m * D_HEAD + k]; };
    auto lb = [&](int n, int k) { return table[n * D_HEAD + k]; };
    auto sc = [&](int m, int n, float v) { out[(size_t)m * NR + n] = v; };
    gemm_ffma2<128, 128, 16, 16, 8>(Mrows, NR, D_HEAD, la, lb, sc);
}

// AWT[n,s,w] = q_word[n,w,:].k_word[n,s,:] + arw[n,w,clip(s-w)] (transposed store)
__global__ void __launch_bounds__(256) k_attn_word() {
    int n = blockIdx.z;
    const float* qw = &g_qw[(size_t)n * TWQ * D_HEAD];
    const float* kw = &g_kw[(size_t)n * TWQ * D_HEAD];
    const float* arw = &g_arw[(size_t)n * TWQ * NR];
    float* out = &g_awt[(size_t)n * TWQ * TWQ];
    auto la4 = [&](int s, int k4) { return ld4(&kw[s * D_HEAD + k4 * 4]); };
    auto lb4 = [&](int w, int k4) { return ld4(&qw[w * D_HEAD + k4 * 4]); };
    auto sc = [&](int s, int w, float v) {
        out[(size_t)s * TWQ + w] = v + arw[w * NR + clip_rel(s - w)];
    };
    gemm_mma<128, 128, 16, 64, 32>(D_HEAD, la4, lb4, sc);
}

// G[n,q,s] = sum_w mapping[b,q,w] * AWT[n,s,w]
__global__ void __launch_bounds__(256) k_G(const float* __restrict__ mapping) {
    int n = blockIdx.z;
    int b = n >> 4;
    const float* Mb = &mapping[(size_t)b * TBQ * TWQ];
    const float* awt = &g_awt[(size_t)n * TWQ * TWQ];
    float* out = &g_G[(size_t)n * TBQ * TWQ];
    auto la4 = [&](int q, int k4) { return ld4(&Mb[(size_t)q * TWQ + k4 * 4]); };
    auto lb4 = [&](int s, int k4) { return ld4(&awt[(size_t)s * TWQ + k4 * 4]); };
    auto sc = [&](int q, int s, float v) { out[(size_t)q * TWQ + s] = v; };
    gemm_mma<128, 128, 16, 64, 32>(TWQ, la4, lb4, sc);
}

// attn[n,q,kc] = q.k (K=64) + G.mapping^T (K=512) + arb[q, clip(kc-q)]
__global__ void __launch_bounds__(256) k_attn(const float* __restrict__ mapping) {
    int n = blockIdx.z;
    int b = n >> 4;
    const float* qb = &g_qb[(size_t)n * TBQ * D_HEAD];
    const float* kb = &g_kb[(size_t)n * TBQ * D_HEAD];
    const float* G = &g_G[(size_t)n * TBQ * TWQ];
    const float* Mb = &mapping[(size_t)b * TBQ * TWQ];
    const float* arb = &g_arb[(size_t)n * TBQ * NR];
    float* out = &g_attn[(size_t)n * TBQ * TBQ];
    auto la4 = [&](int q, int k4) {
        int k = k4 * 4;
        return (k < D_HEAD) ? ld4(&qb[q * D_HEAD + k])
                            : ld4(&G[(size_t)q * TWQ + (k - D_HEAD)]);
    };
    auto lb4 = [&](int kc, int k4) {
        int k = k4 * 4;
        return (k < D_HEAD) ? ld4(&kb[kc * D_HEAD + k])
                            : ld4(&Mb[(size_t)kc * TWQ + (k - D_HEAD)]);
    };
    auto sc = [&](int q, int kc, float v) {
        out[(size_t)q * TBQ + kc] = v + arb[q * NR + clip_rel(kc - q)];
    };
    gemm_mma<128, 128, 16, 64, 32>(D_HEAD + TWQ, la4, lb4, sc);
}

// in-place row softmax over g_attn rows of length 1024. One block per row.
__global__ void k_softmax() {
    __shared__ float red[256];
    size_t row = blockIdx.x;
    float* p = &g_attn[row * TBQ];
    int t = threadIdx.x;
    float4 v = *(float4*)&p[t * 4];
    float m = fmaxf(fmaxf(v.x, v.y), fmaxf(v.z, v.w));
    red[t] = m;
    __syncthreads();
    for (int s = 128; s > 0; s >>= 1) {
        if (t < s) red[t] = fmaxf(red[t], red[t + s]);
        __syncthreads();
    }
    m = red[0];
    __syncthreads();
    v.x = __expf(v.x - m); v.y = __expf(v.y - m);
    v.z = __expf(v.z - m); v.w = __expf(v.w - m);
    red[t] = v.x + v.y + v.z + v.w;
    __syncthreads();
    for (int s = 128; s > 0; s >>= 1) {
        if (t < s) red[t] += red[t + s];
        __syncthreads();
    }
    float inv = 1.f / red[0];
    v.x *= inv; v.y *= inv; v.z *= inv; v.w *= inv;
    *(float4*)&p[t * 4] = v;
}

// ctx[n,q,d] = sum_k probs[n,q,k] * vT[n,d,k]
__global__ void __launch_bounds__(256) k_ctx() {
    int n = blockIdx.z;
    const float* P = &g_attn[(size_t)n * TBQ * TBQ];
    const float* vT = &g_vT[(size_t)n * D_HEAD * TBQ];
    float* out = &g_ctx[(size_t)n * TBQ * D_HEAD];
    auto la4 = [&](int q, int k4) { return ld4(&P[(size_t)q * TBQ + k4 * 4]); };
    auto lb4 = [&](int d, int k4) { return ld4(&vT[(size_t)d * TBQ + k4 * 4]); };
    auto sc = [&](int q, int d, float v) { out[(size_t)q * D_HEAD + d] = v; };
    gemm_mma<128, 64, 16, 32, 32>(TBQ, la4, lb4, sc);
}

// out[t,b,e] = sum_{e'} ctx_heads[t,b,e'] * Wo[e,e'] + bo[e]
__global__ void __launch_bounds__(256)
k_out(const float* __restrict__ Wo, const float* __restrict__ bo,
      float* __restrict__ out) {
    auto la4 = [&](int m, int k4) {
        int k = k4 * 4;
        int t = m >> 2, b = m & 3;
        int nn = b * H_HEADS + (k >> 6);
        int d = k & 63;
        return ld4(&g_ctx[((size_t)nn * TBQ + t) * D_HEAD + d]);
    };
    auto lb4 = [&](int e, int k4) { return ld4(&Wo[(size_t)e * E_DIM + k4 * 4]); };
    auto sc = [&](int m, int e, float v) { out[(size_t)m * E_DIM + e] = v + bo[e]; };
    gemm_mma<128, 128, 16, 64, 32>(E_DIM, la4, lb4, sc);
}

// ---------------- launch ------------------------------------------------------
// dynamic smem: 2 buffers * (Ah+Al+Bh+Bl)
static const int SMEM_MMA128 = 2 * (2 * 16 * 132 + 2 * 16 * 132) * 4;  // 67584
static const int SMEM_MMA64  = 2 * (2 * 16 * 132 + 2 * 16 * 68) * 4;   // 51200

extern "C" void kernel_launch(void* const* d_in, const int* in_sizes, int n_in,
                              void* d_out, int out_size) {
    const float* query_bpe  = (const float*)d_in[0];
    const float* query_word = (const float*)d_in[1];
    const float* mapping    = (const float*)d_in[2];
    const float* Wq_bpe  = (const float*)d_in[3];
    const float* bq_bpe  = (const float*)d_in[4];
    const float* Wk_bpe  = (const float*)d_in[5];
    const float* bk_bpe  = (const float*)d_in[6];
    const float* Wq_word = (const float*)d_in[7];
    const float* bq_word = (const float*)d_in[8];
    const float* Wk_word = (const float*)d_in[9];
    const float* bk_word = (const float*)d_in[10];
    const float* Wv = (const float*)d_in[11];
    const float* bv = (const float*)d_in[12];
    const float* Wo = (const float*)d_in[13];
    const float* bo = (const float*)d_in[14];
    const float* rel_keys = (const float*)d_in[15];
    float* out = (float*)d_out;

    cudaFuncSetAttribute(k_proj, cudaFuncAttributeMaxDynamicSharedMemorySize, SMEM_MMA128);
    cudaFuncSetAttribute(k_attn_word, cudaFuncAttributeMaxDynamicSharedMemorySize, SMEM_MMA128);
    cudaFuncSetAttribute(k_G, cudaFuncAttributeMaxDynamicSharedMemorySize, SMEM_MMA128);
    cudaFuncSetAttribute(k_attn, cudaFuncAttributeMaxDynamicSharedMemorySize, SMEM_MMA128);
    cudaFuncSetAttribute(k_ctx, cudaFuncAttributeMaxDynamicSharedMemorySize, SMEM_MMA64);
    cudaFuncSetAttribute(k_out, cudaFuncAttributeMaxDynamicSharedMemorySize, SMEM_MMA128);

    const int THR = 256;

    // projections -> head layout (M = T*B rows)
    k_proj<<<dim3(8, 32), THR, SMEM_MMA128>>>(query_bpe,  Wq_bpe,  bq_bpe,  SCALE_Q, 0);
    k_proj<<<dim3(8, 32), THR, SMEM_MMA128>>>(query_bpe,  Wk_bpe,  bk_bpe,  1.f,     1);
    k_proj<<<dim3(8, 32), THR, SMEM_MMA128>>>(query_bpe,  Wv,      bv,      1.f,     2);
    k_proj<<<dim3(8, 16), THR, SMEM_MMA128>>>(query_word, Wq_word, bq_word, SCALE_Q, 3);
    k_proj<<<dim3(8, 16), THR, SMEM_MMA128>>>(query_word, Wk_word, bk_word, 1.f,     4);

    // relative-position tables (FFMA2, N=33)
    k_allr<<<dim3(1, 512), 128>>>(rel_keys, 0);
    k_allr<<<dim3(1, 256), 128>>>(rel_keys, 1);

    // word attention logits (transposed), alignment fusion chain
    k_attn_word<<<dim3(4, 4, NH), THR, SMEM_MMA128>>>();
    k_G<<<dim3(4, 8, NH), THR, SMEM_MMA128>>>(mapping);
    k_attn<<<dim3(8, 8, NH), THR, SMEM_MMA128>>>(mapping);

    // softmax over keys
    k_softmax<<<NH * TBQ, 256>>>();

    // probs @ V, output projection
    k_ctx<<<dim3(1, 8, NH), THR, SMEM_MMA64>>>();
    k_out<<<dim3(8, 32), THR, SMEM_MMA128>>>(Wo, bo, out);
}